// round 2
// baseline (speedup 1.0000x reference)
#include <cuda_runtime.h>
#include <math.h>

#define BATCH 1024
#define TSTEPS 80
#define EDIM 100
#define UDIM 256
#define NG 1024   // 4 gates * U

// ---------------- persistent device scratch (no runtime allocation) ----------------
__device__ float g_W1h[UDIM * NG];                  // 256 x 1024 packed, n = u*4+g
__device__ float g_W1x[EDIM * NG];                  // 100 x 1024 packed
__device__ float g_W2 [2 * UDIM * NG];              // 512 x 1024 packed
__device__ float g_b1[NG];
__device__ float g_b2[NG];
__device__ float g_xg[(size_t)TSTEPS * BATCH * NG]; // 335 MB: precomputed x-part of layer1 gates
__device__ float g_h1[2][BATCH * UDIM];
__device__ float g_h2[2][BATCH * UDIM];
__device__ float g_c1[BATCH * UDIM];
__device__ float g_c2[BATCH * UDIM];

__device__ __forceinline__ float sigmoidf_(float x) { return 1.0f / (1.0f + expf(-x)); }

// ---------------- weight repack: n = u*4 + g, g in {f,i,c,o} ----------------
__global__ void pack_kernel(
    const float* wf1, const float* bf1, const float* wi1, const float* bi1,
    const float* wc1, const float* bc1, const float* wo1, const float* bo1,
    const float* wf2, const float* bf2, const float* wi2, const float* bi2,
    const float* wc2, const float* bc2, const float* wo2, const float* bo2)
{
    const int TOT_W = (UDIM + EDIM + 2 * UDIM) * NG;  // 868 * 1024
    int id = blockIdx.x * blockDim.x + threadIdx.x;
    if (id < TOT_W) {
        int kk = id >> 10;
        int n  = id & 1023;
        int u  = n >> 2;
        int g  = n & 3;
        if (kk < UDIM) {
            const float* w = (g == 0) ? wf1 : (g == 1) ? wi1 : (g == 2) ? wc1 : wo1;
            g_W1h[kk * NG + n] = w[kk * UDIM + u];
        } else if (kk < UDIM + EDIM) {
            const float* w = (g == 0) ? wf1 : (g == 1) ? wi1 : (g == 2) ? wc1 : wo1;
            g_W1x[(kk - UDIM) * NG + n] = w[kk * UDIM + u];
        } else {
            int k2 = kk - (UDIM + EDIM);
            const float* w = (g == 0) ? wf2 : (g == 1) ? wi2 : (g == 2) ? wc2 : wo2;
            g_W2[k2 * NG + n] = w[k2 * UDIM + u];
        }
    } else if (id < TOT_W + 2 * NG) {
        int j = id - TOT_W;
        int n = j & 1023;
        int u = n >> 2;
        int g = n & 3;
        if (j < NG) g_b1[n] = ((g == 0) ? bf1 : (g == 1) ? bi1 : (g == 2) ? bc1 : bo1)[u];
        else        g_b2[n] = ((g == 0) ? bf2 : (g == 1) ? bi2 : (g == 2) ? bc2 : bo2)[u];
    }
}

__global__ void zero_kernel()
{
    int id = blockIdx.x * blockDim.x + threadIdx.x;
    if (id < BATCH * UDIM) {
        g_h1[0][id] = 0.0f;
        g_h2[0][id] = 0.0f;
        g_c1[id]    = 0.0f;
        g_c2[id]    = 0.0f;
    }
}

// ---------------- precompute xg = emb[tokens] @ W1x  (M=81920, N=1024, K=100) ----------------
// 64x64 tile, 256 threads, 4x4 micro-tile, kc=32 (K padded to 128 with zero guards)
__global__ __launch_bounds__(256) void xg_kernel(const int* __restrict__ tokens,
                                                 const float* __restrict__ emb)
{
    __shared__ __align__(16) float As[32][64];
    __shared__ __align__(16) float Bs[32][64];

    const int tid = threadIdx.x;
    const int m0  = blockIdx.y * 64;
    const int n0  = blockIdx.x * 64;
    const int tm  = tid >> 4;   // 0..15
    const int tn  = tid & 15;   // 0..15

    float acc[4][4] = {};

    for (int k0 = 0; k0 < 128; k0 += 32) {
        // A tile: 64 rows x 32 k  (gathered embedding rows)
        #pragma unroll
        for (int i = 0; i < 2; i++) {
            int f4 = tid + i * 256;          // 0..511
            int m  = f4 >> 3;                // 0..63
            int kq = f4 & 7;
            int k  = k0 + kq * 4;
            float4 v = make_float4(0.f, 0.f, 0.f, 0.f);
            if (k < EDIM) {
                int mg  = m0 + m;
                int tt  = mg >> 10;          // timestep
                int bb  = mg & 1023;         // batch
                int row = tokens[bb * TSTEPS + tt];
                v = *(const float4*)&emb[(size_t)row * EDIM + k];
            }
            As[kq * 4 + 0][m] = v.x;
            As[kq * 4 + 1][m] = v.y;
            As[kq * 4 + 2][m] = v.z;
            As[kq * 4 + 3][m] = v.w;
        }
        // B tile: 32 k x 64 n
        #pragma unroll
        for (int i = 0; i < 2; i++) {
            int f4 = tid + i * 256;
            int kk = f4 >> 4;
            int c4 = f4 & 15;
            int k  = k0 + kk;
            float4 v = make_float4(0.f, 0.f, 0.f, 0.f);
            if (k < EDIM) v = *(const float4*)&g_W1x[k * NG + n0 + c4 * 4];
            *(float4*)&Bs[kk][c4 * 4] = v;
        }
        __syncthreads();

        #pragma unroll
        for (int k = 0; k < 32; k++) {
            float4 b = *(float4*)&Bs[k][tn * 4];
            float4 a = *(float4*)&As[k][tm * 4];
            float ar[4] = {a.x, a.y, a.z, a.w};
            float br[4] = {b.x, b.y, b.z, b.w};
            #pragma unroll
            for (int r = 0; r < 4; r++)
                #pragma unroll
                for (int c = 0; c < 4; c++)
                    acc[r][c] += ar[r] * br[c];
        }
        __syncthreads();
    }

    #pragma unroll
    for (int r = 0; r < 4; r++) {
        size_t m = (size_t)(m0 + tm * 4 + r);
        float4 v = make_float4(acc[r][0], acc[r][1], acc[r][2], acc[r][3]);
        *(float4*)&g_xg[m * NG + n0 + tn * 4] = v;
    }
}

// ---------------- one LSTM layer step: GEMM (M=1024, N=1024, K=256 or 512) + fused gate update ----------------
// 128x64 tile, 256 threads, 8x4 micro-tile. N micro-tile of 4 = {f,i,c,o} of one unit.
template <bool LAYER2>
__global__ __launch_bounds__(256) void lstm_step(int t, int p)
{
    constexpr int K = LAYER2 ? 2 * UDIM : UDIM;

    __shared__ __align__(16) float As[32][128];
    __shared__ __align__(16) float Bs[32][64];

    const int tid = threadIdx.x;
    const int m0  = blockIdx.y * 128;
    const int n0  = blockIdx.x * 64;
    const int tm  = tid >> 4;   // 0..15 -> 8 rows each
    const int tn  = tid & 15;   // 0..15 -> 4 cols each

    const float* __restrict__ W = LAYER2 ? g_W2 : g_W1h;

    float acc[8][4] = {};

    for (int k0 = 0; k0 < K; k0 += 32) {
        // A tile: 128 rows x 32 k from hidden state(s)
        #pragma unroll
        for (int i = 0; i < 4; i++) {
            int f4 = tid + i * 256;          // 0..1023
            int m  = f4 >> 3;                // 0..127
            int kq = f4 & 7;
            int k  = k0 + kq * 4;
            const float* src;
            if (!LAYER2) {
                src = &g_h1[p][(m0 + m) * UDIM + k];
            } else {
                src = (k < UDIM) ? &g_h2[p][(m0 + m) * UDIM + k]
                                 : &g_h1[1 - p][(m0 + m) * UDIM + (k - UDIM)];
            }
            float4 v = *(const float4*)src;
            As[kq * 4 + 0][m] = v.x;
            As[kq * 4 + 1][m] = v.y;
            As[kq * 4 + 2][m] = v.z;
            As[kq * 4 + 3][m] = v.w;
        }
        // B tile: 32 k x 64 n
        #pragma unroll
        for (int i = 0; i < 2; i++) {
            int f4 = tid + i * 256;
            int kk = f4 >> 4;
            int c4 = f4 & 15;
            *(float4*)&Bs[kk][c4 * 4] = *(const float4*)&W[(k0 + kk) * NG + n0 + c4 * 4];
        }
        __syncthreads();

        #pragma unroll
        for (int k = 0; k < 32; k++) {
            float4 b = *(float4*)&Bs[k][tn * 4];
            float br[4] = {b.x, b.y, b.z, b.w};
            float ar[8];
            float4 a0 = *(float4*)&As[k][tm * 8];
            float4 a1 = *(float4*)&As[k][tm * 8 + 4];
            ar[0] = a0.x; ar[1] = a0.y; ar[2] = a0.z; ar[3] = a0.w;
            ar[4] = a1.x; ar[5] = a1.y; ar[6] = a1.z; ar[7] = a1.w;
            #pragma unroll
            for (int r = 0; r < 8; r++)
                #pragma unroll
                for (int c = 0; c < 4; c++)
                    acc[r][c] += ar[r] * br[c];
        }
        __syncthreads();
    }

    // fused LSTM epilogue
    const float* __restrict__ bias = LAYER2 ? g_b2 : g_b1;
    float* __restrict__ cs   = LAYER2 ? g_c2 : g_c1;
    float* __restrict__ hout = LAYER2 ? g_h2[1 - p] : g_h1[1 - p];

    const int n = n0 + tn * 4;
    const int u = n >> 2;
    float4 bv = *(const float4*)&bias[n];

    #pragma unroll
    for (int r = 0; r < 8; r++) {
        int bb = m0 + tm * 8 + r;
        float pf = acc[r][0] + bv.x;
        float pi = acc[r][1] + bv.y;
        float pc = acc[r][2] + bv.z;
        float po = acc[r][3] + bv.w;
        if (!LAYER2) {
            float4 x = *(const float4*)&g_xg[((size_t)t * BATCH + bb) * NG + n];
            pf += x.x; pi += x.y; pc += x.z; po += x.w;
        }
        float gf = sigmoidf_(pf);
        float gi = sigmoidf_(pi);
        float ct = tanhf(pc);
        float go = sigmoidf_(po);
        float c  = cs[bb * UDIM + u];
        c = gf * c + gi * ct;
        cs[bb * UDIM + u] = c;
        hout[bb * UDIM + u] = go * tanhf(c);
    }
}

// ---------------- final dense + sigmoid: out[b] = sigmoid(h2 . w_out + b_out) ----------------
__global__ void final_kernel(const float* __restrict__ w_out,
                             const float* __restrict__ b_out,
                             float* __restrict__ out)
{
    int warp = threadIdx.x >> 5;
    int lane = threadIdx.x & 31;
    int bb   = blockIdx.x * 8 + warp;   // 128 blocks * 8 warps = 1024
    const float* h = g_h2[0];           // t=79 (odd p) writes buffer 0
    float s = 0.0f;
    #pragma unroll
    for (int i = 0; i < 8; i++) {
        int u = lane + i * 32;
        s += h[bb * UDIM + u] * w_out[u];
    }
    #pragma unroll
    for (int o = 16; o; o >>= 1) s += __shfl_xor_sync(0xFFFFFFFFu, s, o);
    if (lane == 0) out[bb] = sigmoidf_(s + b_out[0]);
}

// ---------------- launch ----------------
extern "C" void kernel_launch(void* const* d_in, const int* in_sizes, int n_in,
                              void* d_out, int out_size)
{
    const int*   tokens = (const int*)  d_in[0];
    const float* emb    = (const float*)d_in[1];
    const float* wf1 = (const float*)d_in[2];  const float* bf1 = (const float*)d_in[3];
    const float* wi1 = (const float*)d_in[4];  const float* bi1 = (const float*)d_in[5];
    const float* wc1 = (const float*)d_in[6];  const float* bc1 = (const float*)d_in[7];
    const float* wo1 = (const float*)d_in[8];  const float* bo1 = (const float*)d_in[9];
    const float* wf2 = (const float*)d_in[10]; const float* bf2 = (const float*)d_in[11];
    const float* wi2 = (const float*)d_in[12]; const float* bi2 = (const float*)d_in[13];
    const float* wc2 = (const float*)d_in[14]; const float* bc2 = (const float*)d_in[15];
    const float* wo2 = (const float*)d_in[16]; const float* bo2 = (const float*)d_in[17];
    const float* w_out = (const float*)d_in[18];
    const float* b_out = (const float*)d_in[19];
    float* out = (float*)d_out;

    const int TOT = (UDIM + EDIM + 2 * UDIM) * NG + 2 * NG;
    pack_kernel<<<(TOT + 255) / 256, 256>>>(wf1, bf1, wi1, bi1, wc1, bc1, wo1, bo1,
                                            wf2, bf2, wi2, bi2, wc2, bc2, wo2, bo2);
    zero_kernel<<<(BATCH * UDIM + 255) / 256, 256>>>();

    // xg precompute: M = T*B = 81920 rows
    xg_kernel<<<dim3(NG / 64, (TSTEPS * BATCH) / 64), 256>>>(tokens, emb);

    for (int t = 0; t < TSTEPS; t++) {
        int p = t & 1;
        lstm_step<false><<<dim3(NG / 64, BATCH / 128), 256>>>(t, p);
        lstm_step<true ><<<dim3(NG / 64, BATCH / 128), 256>>>(t, p);
    }

    final_kernel<<<BATCH / 8, 256>>>(w_out, b_out, out);
}

// round 3
// speedup vs baseline: 1.1109x; 1.1109x over previous
#include <cuda_runtime.h>
#include <math.h>

#define BATCH 1024
#define TSTEPS 80
#define EDIM 100
#define UDIM 256
#define NG 1024       // 4 gates * U
#define VOCAB 10000
#define GRID_CTAS 128
#define NTHR 512

typedef unsigned long long u64;

// ---------------- persistent device scratch (no runtime allocation) ----------------
__device__ float g_W1h[UDIM * NG];                  // 256 x 1024 packed, n = u*4+g
__device__ float g_W1x[EDIM * NG];                  // 100 x 1024 packed
__device__ float g_W2 [2 * UDIM * NG];              // 512 x 1024 packed
__device__ float g_b1[NG];
__device__ float g_b2[NG];
__device__ float g_embW[(size_t)VOCAB * NG];        // 41 MB: emb @ W1x (per-vocab-word gates)
__device__ float g_h1[2][BATCH * UDIM];
__device__ float g_h2[2][BATCH * UDIM];
__device__ float g_c1[BATCH * UDIM];
__device__ float g_c2[BATCH * UDIM];
__device__ unsigned g_bar_count = 0;
__device__ volatile unsigned g_bar_gen = 0;

__device__ __forceinline__ float sigmoidf_(float x) { return 1.0f / (1.0f + expf(-x)); }

// packed f32x2 helpers (SASS FFMA2 path — only reachable via PTX fma.rn.f32x2)
__device__ __forceinline__ void ffma2(u64 &d, u64 a, u64 b) {
    asm("fma.rn.f32x2 %0, %1, %2, %0;" : "+l"(d) : "l"(a), "l"(b));
}
__device__ __forceinline__ u64 pack2(float lo, float hi) {
    u64 r; asm("mov.b64 %0, {%1, %2};" : "=l"(r) : "f"(lo), "f"(hi)); return r;
}
__device__ __forceinline__ u64 dup2(float v) {
    u64 r; asm("mov.b64 %0, {%1, %1};" : "=l"(r) : "f"(v)); return r;
}
__device__ __forceinline__ float lo32(u64 v) { return __uint_as_float((unsigned)v); }
__device__ __forceinline__ float hi32(u64 v) { return __uint_as_float((unsigned)(v >> 32)); }

// ---------------- software grid barrier (all GRID_CTAS co-resident) ----------------
__device__ __forceinline__ void grid_barrier() {
    __syncthreads();
    if (threadIdx.x == 0) {
        __threadfence();
        unsigned gen = g_bar_gen;
        if (atomicAdd(&g_bar_count, 1u) == GRID_CTAS - 1) {
            g_bar_count = 0;
            __threadfence();
            g_bar_gen = gen + 1;
        } else {
            while (g_bar_gen == gen) { }
            __threadfence();
        }
    }
    __syncthreads();
}

// ---------------- weight repack: n = u*4 + g, g in {f,i,c,o} ----------------
__global__ void pack_kernel(
    const float* wf1, const float* bf1, const float* wi1, const float* bi1,
    const float* wc1, const float* bc1, const float* wo1, const float* bo1,
    const float* wf2, const float* bf2, const float* wi2, const float* bi2,
    const float* wc2, const float* bc2, const float* wo2, const float* bo2)
{
    const int TOT_W = (UDIM + EDIM + 2 * UDIM) * NG;
    int id = blockIdx.x * blockDim.x + threadIdx.x;
    if (id < TOT_W) {
        int kk = id >> 10;
        int n  = id & 1023;
        int u  = n >> 2;
        int g  = n & 3;
        if (kk < UDIM) {
            const float* w = (g == 0) ? wf1 : (g == 1) ? wi1 : (g == 2) ? wc1 : wo1;
            g_W1h[kk * NG + n] = w[kk * UDIM + u];
        } else if (kk < UDIM + EDIM) {
            const float* w = (g == 0) ? wf1 : (g == 1) ? wi1 : (g == 2) ? wc1 : wo1;
            g_W1x[(kk - UDIM) * NG + n] = w[kk * UDIM + u];
        } else {
            int k2 = kk - (UDIM + EDIM);
            const float* w = (g == 0) ? wf2 : (g == 1) ? wi2 : (g == 2) ? wc2 : wo2;
            g_W2[k2 * NG + n] = w[k2 * UDIM + u];
        }
    } else if (id < TOT_W + 2 * NG) {
        int j = id - TOT_W;
        int n = j & 1023;
        int u = n >> 2;
        int g = n & 3;
        if (j < NG) g_b1[n] = ((g == 0) ? bf1 : (g == 1) ? bi1 : (g == 2) ? bc1 : bo1)[u];
        else        g_b2[n] = ((g == 0) ? bf2 : (g == 1) ? bi2 : (g == 2) ? bc2 : bo2)[u];
    }
}

__global__ void zero_kernel()
{
    int id = blockIdx.x * blockDim.x + threadIdx.x;
    if (id < BATCH * UDIM) {
        g_h1[0][id] = 0.0f;
        g_h2[0][id] = 0.0f;
        g_c1[id]    = 0.0f;
        g_c2[id]    = 0.0f;
    }
}

// ---------------- embW = emb @ W1x  (M=10000, N=1024, K=100 pad 128) ----------------
__global__ __launch_bounds__(256) void embw_kernel(const float* __restrict__ emb)
{
    __shared__ __align__(16) float As[32][64];
    __shared__ __align__(16) float Bs[32][64];

    const int tid = threadIdx.x;
    const int m0  = blockIdx.y * 64;
    const int n0  = blockIdx.x * 64;
    const int tm  = tid >> 4;
    const int tn  = tid & 15;

    float acc[4][4] = {};

    for (int k0 = 0; k0 < 128; k0 += 32) {
        #pragma unroll
        for (int i = 0; i < 2; i++) {
            int f4 = tid + i * 256;
            int m  = f4 >> 3;
            int kq = f4 & 7;
            int k  = k0 + kq * 4;
            float4 v = make_float4(0.f, 0.f, 0.f, 0.f);
            int row = m0 + m;
            if (k < EDIM && row < VOCAB)
                v = *(const float4*)&emb[(size_t)row * EDIM + k];
            As[kq * 4 + 0][m] = v.x;
            As[kq * 4 + 1][m] = v.y;
            As[kq * 4 + 2][m] = v.z;
            As[kq * 4 + 3][m] = v.w;
        }
        #pragma unroll
        for (int i = 0; i < 2; i++) {
            int f4 = tid + i * 256;
            int kk = f4 >> 4;
            int c4 = f4 & 15;
            int k  = k0 + kk;
            float4 v = make_float4(0.f, 0.f, 0.f, 0.f);
            if (k < EDIM) v = *(const float4*)&g_W1x[k * NG + n0 + c4 * 4];
            *(float4*)&Bs[kk][c4 * 4] = v;
        }
        __syncthreads();

        #pragma unroll
        for (int k = 0; k < 32; k++) {
            float4 b = *(const float4*)&Bs[k][tn * 4];
            float4 a = *(const float4*)&As[k][tm * 4];
            float ar[4] = {a.x, a.y, a.z, a.w};
            float br[4] = {b.x, b.y, b.z, b.w};
            #pragma unroll
            for (int r = 0; r < 4; r++)
                #pragma unroll
                for (int c = 0; c < 4; c++)
                    acc[r][c] += ar[r] * br[c];
        }
        __syncthreads();
    }

    #pragma unroll
    for (int r = 0; r < 4; r++) {
        int row = m0 + tm * 4 + r;
        if (row < VOCAB)
            *(float4*)&g_embW[(size_t)row * NG + n0 + tn * 4] =
                make_float4(acc[r][0], acc[r][1], acc[r][2], acc[r][3]);
    }
}

// ---------------- one layer phase: 128x64 tile GEMM (f32x2) + fused LSTM epilogue ----------------
template <bool LAYER2>
__device__ __forceinline__ void phase(int t, int p, int m0, int n0, int tm, int tn,
                                      float (*As)[128], float (*Bs)[64],
                                      const int* __restrict__ tokens)
{
    const int tid = threadIdx.x;
    constexpr int K = LAYER2 ? 2 * UDIM : UDIM;
    const float* __restrict__ W = LAYER2 ? g_W2 : g_W1h;

    u64 acc[2][4];
    #pragma unroll
    for (int r = 0; r < 2; r++)
        #pragma unroll
        for (int c = 0; c < 4; c++) acc[r][c] = 0ull;

    for (int k0 = 0; k0 < K; k0 += 32) {
        // A tile: 128 rows x 32 k of hidden state (4096 floats / 512 thr = 2 float4 each)
        #pragma unroll
        for (int i = 0; i < 2; i++) {
            int f4 = tid + i * NTHR;         // 0..1023
            int m  = f4 >> 3;                // 0..127
            int kq = f4 & 7;
            int k  = k0 + kq * 4;
            const float* src;
            if (!LAYER2) {
                src = &g_h1[p][(m0 + m) * UDIM + k];
            } else {
                src = (k < UDIM) ? &g_h2[p][(m0 + m) * UDIM + k]
                                 : &g_h1[1 - p][(m0 + m) * UDIM + (k - UDIM)];
            }
            float4 v = *(const float4*)src;
            As[kq * 4 + 0][m] = v.x;
            As[kq * 4 + 1][m] = v.y;
            As[kq * 4 + 2][m] = v.z;
            As[kq * 4 + 3][m] = v.w;
        }
        // B tile: 32 k x 64 n (2048 floats / 512 thr = 1 float4 each)
        {
            int kk = tid >> 4;               // 0..31
            int c4 = tid & 15;               // 0..15
            *(float4*)&Bs[kk][c4 * 4] = *(const float4*)&W[(k0 + kk) * NG + n0 + c4 * 4];
        }
        __syncthreads();

        #pragma unroll
        for (int k = 0; k < 32; k++) {
            float4 Af = *(const float4*)&As[k][tm * 4];
            float4 Bf = *(const float4*)&Bs[k][tn * 4];
            u64 a0 = pack2(Af.x, Af.y);
            u64 a1 = pack2(Af.z, Af.w);
            u64 b0 = dup2(Bf.x), b1 = dup2(Bf.y), b2 = dup2(Bf.z), b3 = dup2(Bf.w);
            ffma2(acc[0][0], a0, b0); ffma2(acc[0][1], a0, b1);
            ffma2(acc[0][2], a0, b2); ffma2(acc[0][3], a0, b3);
            ffma2(acc[1][0], a1, b0); ffma2(acc[1][1], a1, b1);
            ffma2(acc[1][2], a1, b2); ffma2(acc[1][3], a1, b3);
        }
        __syncthreads();
    }

    // fused LSTM epilogue: this thread owns 4 batch rows x unit u
    const float* __restrict__ bias = LAYER2 ? g_b2 : g_b1;
    float* __restrict__ cs   = LAYER2 ? g_c2 : g_c1;
    float* __restrict__ hout = LAYER2 ? g_h2[1 - p] : g_h1[1 - p];

    const int n = n0 + tn * 4;
    const int u = n >> 2;
    float4 bv = *(const float4*)&bias[n];

    #pragma unroll
    for (int r = 0; r < 4; r++) {
        int bb = m0 + tm * 4 + r;
        int rp = r >> 1;
        float pf = ((r & 1) ? hi32(acc[rp][0]) : lo32(acc[rp][0])) + bv.x;
        float pi = ((r & 1) ? hi32(acc[rp][1]) : lo32(acc[rp][1])) + bv.y;
        float pc = ((r & 1) ? hi32(acc[rp][2]) : lo32(acc[rp][2])) + bv.z;
        float po = ((r & 1) ? hi32(acc[rp][3]) : lo32(acc[rp][3])) + bv.w;
        if (!LAYER2) {
            int row = tokens[bb * TSTEPS + t];
            float4 x = *(const float4*)&g_embW[(size_t)row * NG + n];
            pf += x.x; pi += x.y; pc += x.z; po += x.w;
        }
        float gf = sigmoidf_(pf);
        float gi = sigmoidf_(pi);
        float ct = tanhf(pc);
        float go = sigmoidf_(po);
        float c  = cs[bb * UDIM + u];
        c = gf * c + gi * ct;
        cs[bb * UDIM + u] = c;
        hout[bb * UDIM + u] = go * tanhf(c);
    }
}

// ---------------- persistent all-timesteps kernel ----------------
__global__ __launch_bounds__(NTHR, 1) void lstm_persistent(
    const int* __restrict__ tokens,
    const float* __restrict__ w_out, const float* __restrict__ b_out,
    float* __restrict__ out)
{
    __shared__ __align__(16) float As[32][128];
    __shared__ __align__(16) float Bs[32][64];

    const int cta = blockIdx.x;
    const int n0  = (cta & 15) * 64;
    const int m0  = (cta >> 4) * 128;
    const int tm  = threadIdx.x >> 4;    // 0..31
    const int tn  = threadIdx.x & 15;    // 0..15

    for (int t = 0; t < TSTEPS; t++) {
        int p = t & 1;
        phase<false>(t, p, m0, n0, tm, tn, As, Bs, tokens);
        grid_barrier();
        phase<true >(t, p, m0, n0, tm, tn, As, Bs, tokens);
        grid_barrier();
    }

    // final dense + sigmoid: 8 batches per CTA (warps 0-7)
    int warp = threadIdx.x >> 5;
    int lane = threadIdx.x & 31;
    if (warp < 8) {
        int bb = cta * 8 + warp;
        const float* h = g_h2[0];        // t=79 (p=1) wrote buffer 0
        float s = 0.0f;
        #pragma unroll
        for (int i = 0; i < 8; i++)
            s += h[bb * UDIM + lane + i * 32] * w_out[lane + i * 32];
        #pragma unroll
        for (int o = 16; o; o >>= 1) s += __shfl_xor_sync(0xFFFFFFFFu, s, o);
        if (lane == 0) out[bb] = sigmoidf_(s + b_out[0]);
    }
}

// ---------------- launch ----------------
extern "C" void kernel_launch(void* const* d_in, const int* in_sizes, int n_in,
                              void* d_out, int out_size)
{
    const int*   tokens = (const int*)  d_in[0];
    const float* emb    = (const float*)d_in[1];
    const float* wf1 = (const float*)d_in[2];  const float* bf1 = (const float*)d_in[3];
    const float* wi1 = (const float*)d_in[4];  const float* bi1 = (const float*)d_in[5];
    const float* wc1 = (const float*)d_in[6];  const float* bc1 = (const float*)d_in[7];
    const float* wo1 = (const float*)d_in[8];  const float* bo1 = (const float*)d_in[9];
    const float* wf2 = (const float*)d_in[10]; const float* bf2 = (const float*)d_in[11];
    const float* wi2 = (const float*)d_in[12]; const float* bi2 = (const float*)d_in[13];
    const float* wc2 = (const float*)d_in[14]; const float* bc2 = (const float*)d_in[15];
    const float* wo2 = (const float*)d_in[16]; const float* bo2 = (const float*)d_in[17];
    const float* w_out = (const float*)d_in[18];
    const float* b_out = (const float*)d_in[19];
    float* out = (float*)d_out;

    const int TOT = (UDIM + EDIM + 2 * UDIM) * NG + 2 * NG;
    pack_kernel<<<(TOT + 255) / 256, 256>>>(wf1, bf1, wi1, bi1, wc1, bc1, wo1, bo1,
                                            wf2, bf2, wi2, bi2, wc2, bc2, wo2, bo2);
    zero_kernel<<<(BATCH * UDIM + 255) / 256, 256>>>();

    // embW = emb @ W1x  (V=10000 rows -> replaces the 81920-row xg GEMM)
    embw_kernel<<<dim3(NG / 64, (VOCAB + 63) / 64), 256>>>(emb);

    lstm_persistent<<<GRID_CTAS, NTHR>>>(tokens, w_out, b_out, out);
}

// round 4
// speedup vs baseline: 1.1129x; 1.0018x over previous
#include <cuda_runtime.h>
#include <math.h>

#define BATCH 1024
#define TSTEPS 80
#define EDIM 100
#define UDIM 256
#define NG 1024       // 4 gates * U
#define VOCAB 10000
#define GRID_CTAS 128
#define NTHR 512

typedef unsigned long long u64;

// ---------------- persistent device scratch (no runtime allocation) ----------------
__device__ float g_W1h[UDIM * NG];                  // 256 x 1024 packed, n = u*4+g
__device__ float g_W1x[EDIM * NG];                  // 100 x 1024 packed
__device__ float g_W2 [2 * UDIM * NG];              // 512 x 1024 packed
__device__ float g_b1[NG];
__device__ float g_b2[NG];
__device__ float g_embW[(size_t)VOCAB * NG];        // 41 MB: emb @ W1x (per-vocab-word gates)
__device__ float g_h1[2][BATCH * UDIM];
__device__ float g_h2[2][BATCH * UDIM];
__device__ float g_c1[BATCH * UDIM];
__device__ float g_c2[BATCH * UDIM];
__device__ unsigned g_bar_count = 0;
__device__ volatile unsigned g_bar_gen = 0;

__device__ __forceinline__ float sigmoidf_(float x) { return 1.0f / (1.0f + expf(-x)); }

// packed f32x2 helpers (SASS FFMA2 path — only reachable via PTX fma.rn.f32x2)
__device__ __forceinline__ void ffma2(u64 &d, u64 a, u64 b) {
    asm("fma.rn.f32x2 %0, %1, %2, %0;" : "+l"(d) : "l"(a), "l"(b));
}
__device__ __forceinline__ u64 pack2(float lo, float hi) {
    u64 r; asm("mov.b64 %0, {%1, %2};" : "=l"(r) : "f"(lo), "f"(hi)); return r;
}
__device__ __forceinline__ u64 dup2(float v) {
    u64 r; asm("mov.b64 %0, {%1, %1};" : "=l"(r) : "f"(v)); return r;
}
__device__ __forceinline__ float lo32(u64 v) { return __uint_as_float((unsigned)v); }
__device__ __forceinline__ float hi32(u64 v) { return __uint_as_float((unsigned)(v >> 32)); }

// ---------------- software grid barrier (all GRID_CTAS co-resident) ----------------
__device__ __forceinline__ void grid_barrier() {
    __syncthreads();
    if (threadIdx.x == 0) {
        __threadfence();
        unsigned gen = g_bar_gen;
        if (atomicAdd(&g_bar_count, 1u) == GRID_CTAS - 1) {
            g_bar_count = 0;
            __threadfence();
            g_bar_gen = gen + 1;
        } else {
            while (g_bar_gen == gen) { }
            __threadfence();
        }
    }
    __syncthreads();
}

// ---------------- weight repack: n = u*4 + g, g in {f,i,c,o} ----------------
__global__ void pack_kernel(
    const float* wf1, const float* bf1, const float* wi1, const float* bi1,
    const float* wc1, const float* bc1, const float* wo1, const float* bo1,
    const float* wf2, const float* bf2, const float* wi2, const float* bi2,
    const float* wc2, const float* bc2, const float* wo2, const float* bo2)
{
    const int TOT_W = (UDIM + EDIM + 2 * UDIM) * NG;
    int id = blockIdx.x * blockDim.x + threadIdx.x;
    if (id < TOT_W) {
        int kk = id >> 10;
        int n  = id & 1023;
        int u  = n >> 2;
        int g  = n & 3;
        if (kk < UDIM) {
            const float* w = (g == 0) ? wf1 : (g == 1) ? wi1 : (g == 2) ? wc1 : wo1;
            g_W1h[kk * NG + n] = w[kk * UDIM + u];
        } else if (kk < UDIM + EDIM) {
            const float* w = (g == 0) ? wf1 : (g == 1) ? wi1 : (g == 2) ? wc1 : wo1;
            g_W1x[(kk - UDIM) * NG + n] = w[kk * UDIM + u];
        } else {
            int k2 = kk - (UDIM + EDIM);
            const float* w = (g == 0) ? wf2 : (g == 1) ? wi2 : (g == 2) ? wc2 : wo2;
            g_W2[k2 * NG + n] = w[k2 * UDIM + u];
        }
    } else if (id < TOT_W + 2 * NG) {
        int j = id - TOT_W;
        int n = j & 1023;
        int u = n >> 2;
        int g = n & 3;
        if (j < NG) g_b1[n] = ((g == 0) ? bf1 : (g == 1) ? bi1 : (g == 2) ? bc1 : bo1)[u];
        else        g_b2[n] = ((g == 0) ? bf2 : (g == 1) ? bi2 : (g == 2) ? bc2 : bo2)[u];
    }
}

__global__ void zero_kernel()
{
    int id = blockIdx.x * blockDim.x + threadIdx.x;
    if (id < BATCH * UDIM) {
        g_h1[0][id] = 0.0f;
        g_h2[0][id] = 0.0f;
        g_c1[id]    = 0.0f;
        g_c2[id]    = 0.0f;
    }
}

// ---------------- embW = emb @ W1x  (M=10000, N=1024, K=100 pad 128) ----------------
__global__ __launch_bounds__(256) void embw_kernel(const float* __restrict__ emb)
{
    __shared__ __align__(16) float As[32][64];
    __shared__ __align__(16) float Bs[32][64];

    const int tid = threadIdx.x;
    const int m0  = blockIdx.y * 64;
    const int n0  = blockIdx.x * 64;
    const int tm  = tid >> 4;
    const int tn  = tid & 15;

    float acc[4][4] = {};

    for (int k0 = 0; k0 < 128; k0 += 32) {
        #pragma unroll
        for (int i = 0; i < 2; i++) {
            int f4 = tid + i * 256;
            int m  = f4 >> 3;
            int kq = f4 & 7;
            int k  = k0 + kq * 4;
            float4 v = make_float4(0.f, 0.f, 0.f, 0.f);
            int row = m0 + m;
            if (k < EDIM && row < VOCAB)
                v = *(const float4*)&emb[(size_t)row * EDIM + k];
            As[kq * 4 + 0][m] = v.x;
            As[kq * 4 + 1][m] = v.y;
            As[kq * 4 + 2][m] = v.z;
            As[kq * 4 + 3][m] = v.w;
        }
        #pragma unroll
        for (int i = 0; i < 2; i++) {
            int f4 = tid + i * 256;
            int kk = f4 >> 4;
            int c4 = f4 & 15;
            int k  = k0 + kk;
            float4 v = make_float4(0.f, 0.f, 0.f, 0.f);
            if (k < EDIM) v = *(const float4*)&g_W1x[k * NG + n0 + c4 * 4];
            *(float4*)&Bs[kk][c4 * 4] = v;
        }
        __syncthreads();

        #pragma unroll
        for (int k = 0; k < 32; k++) {
            float4 b = *(const float4*)&Bs[k][tn * 4];
            float4 a = *(const float4*)&As[k][tm * 4];
            float ar[4] = {a.x, a.y, a.z, a.w};
            float br[4] = {b.x, b.y, b.z, b.w};
            #pragma unroll
            for (int r = 0; r < 4; r++)
                #pragma unroll
                for (int c = 0; c < 4; c++)
                    acc[r][c] += ar[r] * br[c];
        }
        __syncthreads();
    }

    #pragma unroll
    for (int r = 0; r < 4; r++) {
        int row = m0 + tm * 4 + r;
        if (row < VOCAB)
            *(float4*)&g_embW[(size_t)row * NG + n0 + tn * 4] =
                make_float4(acc[r][0], acc[r][1], acc[r][2], acc[r][3]);
    }
}

// ---------------- one layer phase: 128x64 tile GEMM (f32x2) + fused LSTM epilogue ----------------
template <bool LAYER2>
__device__ __forceinline__ void phase(int t, int p, int m0, int n0, int tm, int tn,
                                      float (*As)[128], float (*Bs)[64],
                                      const int* __restrict__ tokens)
{
    const int tid = threadIdx.x;
    constexpr int K = LAYER2 ? 2 * UDIM : UDIM;
    const float* __restrict__ W = LAYER2 ? g_W2 : g_W1h;

    u64 acc[2][4];
    #pragma unroll
    for (int r = 0; r < 2; r++)
        #pragma unroll
        for (int c = 0; c < 4; c++) acc[r][c] = 0ull;

    for (int k0 = 0; k0 < K; k0 += 32) {
        // A tile: 128 rows x 32 k of hidden state (4096 floats / 512 thr = 2 float4 each)
        #pragma unroll
        for (int i = 0; i < 2; i++) {
            int f4 = tid + i * NTHR;         // 0..1023
            int m  = f4 >> 3;                // 0..127
            int kq = f4 & 7;
            int k  = k0 + kq * 4;
            const float* src;
            if (!LAYER2) {
                src = &g_h1[p][(m0 + m) * UDIM + k];
            } else {
                src = (k < UDIM) ? &g_h2[p][(m0 + m) * UDIM + k]
                                 : &g_h1[1 - p][(m0 + m) * UDIM + (k - UDIM)];
            }
            float4 v = *(const float4*)src;
            As[kq * 4 + 0][m] = v.x;
            As[kq * 4 + 1][m] = v.y;
            As[kq * 4 + 2][m] = v.z;
            As[kq * 4 + 3][m] = v.w;
        }
        // B tile: 32 k x 64 n (2048 floats / 512 thr = 1 float4 each)
        {
            int kk = tid >> 4;               // 0..31
            int c4 = tid & 15;               // 0..15
            *(float4*)&Bs[kk][c4 * 4] = *(const float4*)&W[(k0 + kk) * NG + n0 + c4 * 4];
        }
        __syncthreads();

        #pragma unroll
        for (int k = 0; k < 32; k++) {
            float4 Af = *(const float4*)&As[k][tm * 4];
            float4 Bf = *(const float4*)&Bs[k][tn * 4];
            u64 a0 = pack2(Af.x, Af.y);
            u64 a1 = pack2(Af.z, Af.w);
            u64 b0 = dup2(Bf.x), b1 = dup2(Bf.y), b2 = dup2(Bf.z), b3 = dup2(Bf.w);
            ffma2(acc[0][0], a0, b0); ffma2(acc[0][1], a0, b1);
            ffma2(acc[0][2], a0, b2); ffma2(acc[0][3], a0, b3);
            ffma2(acc[1][0], a1, b0); ffma2(acc[1][1], a1, b1);
            ffma2(acc[1][2], a1, b2); ffma2(acc[1][3], a1, b3);
        }
        __syncthreads();
    }

    // fused LSTM epilogue: this thread owns 4 batch rows x unit u
    const float* __restrict__ bias = LAYER2 ? g_b2 : g_b1;
    float* __restrict__ cs   = LAYER2 ? g_c2 : g_c1;
    float* __restrict__ hout = LAYER2 ? g_h2[1 - p] : g_h1[1 - p];

    const int n = n0 + tn * 4;
    const int u = n >> 2;
    float4 bv = *(const float4*)&bias[n];

    #pragma unroll
    for (int r = 0; r < 4; r++) {
        int bb = m0 + tm * 4 + r;
        int rp = r >> 1;
        float pf = ((r & 1) ? hi32(acc[rp][0]) : lo32(acc[rp][0])) + bv.x;
        float pi = ((r & 1) ? hi32(acc[rp][1]) : lo32(acc[rp][1])) + bv.y;
        float pc = ((r & 1) ? hi32(acc[rp][2]) : lo32(acc[rp][2])) + bv.z;
        float po = ((r & 1) ? hi32(acc[rp][3]) : lo32(acc[rp][3])) + bv.w;
        if (!LAYER2) {
            int row = tokens[bb * TSTEPS + t];
            float4 x = *(const float4*)&g_embW[(size_t)row * NG + n];
            pf += x.x; pi += x.y; pc += x.z; po += x.w;
        }
        float gf = sigmoidf_(pf);
        float gi = sigmoidf_(pi);
        float ct = tanhf(pc);
        float go = sigmoidf_(po);
        float c  = cs[bb * UDIM + u];
        c = gf * c + gi * ct;
        cs[bb * UDIM + u] = c;
        hout[bb * UDIM + u] = go * tanhf(c);
    }
}

// ---------------- persistent all-timesteps kernel ----------------
__global__ __launch_bounds__(NTHR, 1) void lstm_persistent(
    const int* __restrict__ tokens,
    const float* __restrict__ w_out, const float* __restrict__ b_out,
    float* __restrict__ out)
{
    __shared__ __align__(16) float As[32][128];
    __shared__ __align__(16) float Bs[32][64];

    const int cta = blockIdx.x;
    const int n0  = (cta & 15) * 64;
    const int m0  = (cta >> 4) * 128;
    const int tm  = threadIdx.x >> 4;    // 0..31
    const int tn  = threadIdx.x & 15;    // 0..15

    for (int t = 0; t < TSTEPS; t++) {
        int p = t & 1;
        phase<false>(t, p, m0, n0, tm, tn, As, Bs, tokens);
        grid_barrier();
        phase<true >(t, p, m0, n0, tm, tn, As, Bs, tokens);
        grid_barrier();
    }

    // final dense + sigmoid: 8 batches per CTA (warps 0-7)
    int warp = threadIdx.x >> 5;
    int lane = threadIdx.x & 31;
    if (warp < 8) {
        int bb = cta * 8 + warp;
        const float* h = g_h2[0];        // t=79 (p=1) wrote buffer 0
        float s = 0.0f;
        #pragma unroll
        for (int i = 0; i < 8; i++)
            s += h[bb * UDIM + lane + i * 32] * w_out[lane + i * 32];
        #pragma unroll
        for (int o = 16; o; o >>= 1) s += __shfl_xor_sync(0xFFFFFFFFu, s, o);
        if (lane == 0) out[bb] = sigmoidf_(s + b_out[0]);
    }
}

// ---------------- launch ----------------
extern "C" void kernel_launch(void* const* d_in, const int* in_sizes, int n_in,
                              void* d_out, int out_size)
{
    const int*   tokens = (const int*)  d_in[0];
    const float* emb    = (const float*)d_in[1];
    const float* wf1 = (const float*)d_in[2];  const float* bf1 = (const float*)d_in[3];
    const float* wi1 = (const float*)d_in[4];  const float* bi1 = (const float*)d_in[5];
    const float* wc1 = (const float*)d_in[6];  const float* bc1 = (const float*)d_in[7];
    const float* wo1 = (const float*)d_in[8];  const float* bo1 = (const float*)d_in[9];
    const float* wf2 = (const float*)d_in[10]; const float* bf2 = (const float*)d_in[11];
    const float* wi2 = (const float*)d_in[12]; const float* bi2 = (const float*)d_in[13];
    const float* wc2 = (const float*)d_in[14]; const float* bc2 = (const float*)d_in[15];
    const float* wo2 = (const float*)d_in[16]; const float* bo2 = (const float*)d_in[17];
    const float* w_out = (const float*)d_in[18];
    const float* b_out = (const float*)d_in[19];
    float* out = (float*)d_out;

    const int TOT = (UDIM + EDIM + 2 * UDIM) * NG + 2 * NG;
    pack_kernel<<<(TOT + 255) / 256, 256>>>(wf1, bf1, wi1, bi1, wc1, bc1, wo1, bo1,
                                            wf2, bf2, wi2, bi2, wc2, bc2, wo2, bo2);
    zero_kernel<<<(BATCH * UDIM + 255) / 256, 256>>>();

    // embW = emb @ W1x  (V=10000 rows -> replaces the 81920-row xg GEMM)
    embw_kernel<<<dim3(NG / 64, (VOCAB + 63) / 64), 256>>>(emb);

    lstm_persistent<<<GRID_CTAS, NTHR>>>(tokens, w_out, b_out, out);
}

// round 5
// speedup vs baseline: 1.1131x; 1.0002x over previous
#include <cuda_runtime.h>
#include <math.h>

#define BATCH 1024
#define TSTEPS 80
#define EDIM 100
#define UDIM 256
#define NG 1024       // 4 gates * U
#define VOCAB 10000
#define GRID_CTAS 128
#define NTHR 512

typedef unsigned long long u64;

// ---------------- persistent device scratch (no runtime allocation) ----------------
__device__ float g_W1h[UDIM * NG];                  // 256 x 1024 packed, n = u*4+g
__device__ float g_W1x[EDIM * NG];                  // 100 x 1024 packed
__device__ float g_W2 [2 * UDIM * NG];              // 512 x 1024 packed
__device__ float g_b1[NG];
__device__ float g_b2[NG];
__device__ float g_embW[(size_t)VOCAB * NG];        // 41 MB: emb @ W1x (per-vocab-word gates)
__device__ float g_h1[2][BATCH * UDIM];
__device__ float g_h2[2][BATCH * UDIM];
__device__ float g_c1[BATCH * UDIM];
__device__ float g_c2[BATCH * UDIM];
__device__ unsigned g_bar_count = 0;
__device__ volatile unsigned g_bar_gen = 0;

__device__ __forceinline__ float sigmoidf_(float x) { return 1.0f / (1.0f + expf(-x)); }

// packed f32x2 helpers (SASS FFMA2 path — only reachable via PTX fma.rn.f32x2)
__device__ __forceinline__ void ffma2(u64 &d, u64 a, u64 b) {
    asm("fma.rn.f32x2 %0, %1, %2, %0;" : "+l"(d) : "l"(a), "l"(b));
}
__device__ __forceinline__ u64 pack2(float lo, float hi) {
    u64 r; asm("mov.b64 %0, {%1, %2};" : "=l"(r) : "f"(lo), "f"(hi)); return r;
}
__device__ __forceinline__ u64 dup2(float v) {
    u64 r; asm("mov.b64 %0, {%1, %1};" : "=l"(r) : "f"(v)); return r;
}
__device__ __forceinline__ float lo32(u64 v) { return __uint_as_float((unsigned)v); }
__device__ __forceinline__ float hi32(u64 v) { return __uint_as_float((unsigned)(v >> 32)); }

// ---------------- software grid barrier (all GRID_CTAS co-resident) ----------------
__device__ __forceinline__ void grid_barrier() {
    __syncthreads();
    if (threadIdx.x == 0) {
        __threadfence();
        unsigned gen = g_bar_gen;
        if (atomicAdd(&g_bar_count, 1u) == GRID_CTAS - 1) {
            g_bar_count = 0;
            __threadfence();
            g_bar_gen = gen + 1;
        } else {
            while (g_bar_gen == gen) { }
            __threadfence();
        }
    }
    __syncthreads();
}

// ---------------- weight repack: n = u*4 + g, g in {f,i,c,o} ----------------
__global__ void pack_kernel(
    const float* wf1, const float* bf1, const float* wi1, const float* bi1,
    const float* wc1, const float* bc1, const float* wo1, const float* bo1,
    const float* wf2, const float* bf2, const float* wi2, const float* bi2,
    const float* wc2, const float* bc2, const float* wo2, const float* bo2)
{
    const int TOT_W = (UDIM + EDIM + 2 * UDIM) * NG;
    int id = blockIdx.x * blockDim.x + threadIdx.x;
    if (id < TOT_W) {
        int kk = id >> 10;
        int n  = id & 1023;
        int u  = n >> 2;
        int g  = n & 3;
        if (kk < UDIM) {
            const float* w = (g == 0) ? wf1 : (g == 1) ? wi1 : (g == 2) ? wc1 : wo1;
            g_W1h[kk * NG + n] = w[kk * UDIM + u];
        } else if (kk < UDIM + EDIM) {
            const float* w = (g == 0) ? wf1 : (g == 1) ? wi1 : (g == 2) ? wc1 : wo1;
            g_W1x[(kk - UDIM) * NG + n] = w[kk * UDIM + u];
        } else {
            int k2 = kk - (UDIM + EDIM);
            const float* w = (g == 0) ? wf2 : (g == 1) ? wi2 : (g == 2) ? wc2 : wo2;
            g_W2[k2 * NG + n] = w[k2 * UDIM + u];
        }
    } else if (id < TOT_W + 2 * NG) {
        int j = id - TOT_W;
        int n = j & 1023;
        int u = n >> 2;
        int g = n & 3;
        if (j < NG) g_b1[n] = ((g == 0) ? bf1 : (g == 1) ? bi1 : (g == 2) ? bc1 : bo1)[u];
        else        g_b2[n] = ((g == 0) ? bf2 : (g == 1) ? bi2 : (g == 2) ? bc2 : bo2)[u];
    }
}

__global__ void zero_kernel()
{
    int id = blockIdx.x * blockDim.x + threadIdx.x;
    if (id < BATCH * UDIM) {
        g_h1[0][id] = 0.0f;
        g_h2[0][id] = 0.0f;
        g_c1[id]    = 0.0f;
        g_c2[id]    = 0.0f;
    }
}

// ---------------- embW = emb @ W1x  (M=10000, N=1024, K=100 pad 128) ----------------
__global__ __launch_bounds__(256) void embw_kernel(const float* __restrict__ emb)
{
    __shared__ __align__(16) float As[32][64];
    __shared__ __align__(16) float Bs[32][64];

    const int tid = threadIdx.x;
    const int m0  = blockIdx.y * 64;
    const int n0  = blockIdx.x * 64;
    const int tm  = tid >> 4;
    const int tn  = tid & 15;

    float acc[4][4] = {};

    for (int k0 = 0; k0 < 128; k0 += 32) {
        #pragma unroll
        for (int i = 0; i < 2; i++) {
            int f4 = tid + i * 256;
            int m  = f4 >> 3;
            int kq = f4 & 7;
            int k  = k0 + kq * 4;
            float4 v = make_float4(0.f, 0.f, 0.f, 0.f);
            int row = m0 + m;
            if (k < EDIM && row < VOCAB)
                v = *(const float4*)&emb[(size_t)row * EDIM + k];
            As[kq * 4 + 0][m] = v.x;
            As[kq * 4 + 1][m] = v.y;
            As[kq * 4 + 2][m] = v.z;
            As[kq * 4 + 3][m] = v.w;
        }
        #pragma unroll
        for (int i = 0; i < 2; i++) {
            int f4 = tid + i * 256;
            int kk = f4 >> 4;
            int c4 = f4 & 15;
            int k  = k0 + kk;
            float4 v = make_float4(0.f, 0.f, 0.f, 0.f);
            if (k < EDIM) v = *(const float4*)&g_W1x[k * NG + n0 + c4 * 4];
            *(float4*)&Bs[kk][c4 * 4] = v;
        }
        __syncthreads();

        #pragma unroll
        for (int k = 0; k < 32; k++) {
            float4 b = *(const float4*)&Bs[k][tn * 4];
            float4 a = *(const float4*)&As[k][tm * 4];
            float ar[4] = {a.x, a.y, a.z, a.w};
            float br[4] = {b.x, b.y, b.z, b.w};
            #pragma unroll
            for (int r = 0; r < 4; r++)
                #pragma unroll
                for (int c = 0; c < 4; c++)
                    acc[r][c] += ar[r] * br[c];
        }
        __syncthreads();
    }

    #pragma unroll
    for (int r = 0; r < 4; r++) {
        int row = m0 + tm * 4 + r;
        if (row < VOCAB)
            *(float4*)&g_embW[(size_t)row * NG + n0 + tn * 4] =
                make_float4(acc[r][0], acc[r][1], acc[r][2], acc[r][3]);
    }
}

// ---------------- one layer phase: 128x64 tile GEMM (f32x2) + fused LSTM epilogue ----------------
template <bool LAYER2>
__device__ __forceinline__ void phase(int t, int p, int m0, int n0, int tm, int tn,
                                      float (*As)[128], float (*Bs)[64],
                                      const int* __restrict__ tokens)
{
    const int tid = threadIdx.x;
    constexpr int K = LAYER2 ? 2 * UDIM : UDIM;
    const float* __restrict__ W = LAYER2 ? g_W2 : g_W1h;

    u64 acc[2][4];
    #pragma unroll
    for (int r = 0; r < 2; r++)
        #pragma unroll
        for (int c = 0; c < 4; c++) acc[r][c] = 0ull;

    for (int k0 = 0; k0 < K; k0 += 32) {
        // A tile: 128 rows x 32 k of hidden state (4096 floats / 512 thr = 2 float4 each)
        #pragma unroll
        for (int i = 0; i < 2; i++) {
            int f4 = tid + i * NTHR;         // 0..1023
            int m  = f4 >> 3;                // 0..127
            int kq = f4 & 7;
            int k  = k0 + kq * 4;
            const float* src;
            if (!LAYER2) {
                src = &g_h1[p][(m0 + m) * UDIM + k];
            } else {
                src = (k < UDIM) ? &g_h2[p][(m0 + m) * UDIM + k]
                                 : &g_h1[1 - p][(m0 + m) * UDIM + (k - UDIM)];
            }
            float4 v = *(const float4*)src;
            As[kq * 4 + 0][m] = v.x;
            As[kq * 4 + 1][m] = v.y;
            As[kq * 4 + 2][m] = v.z;
            As[kq * 4 + 3][m] = v.w;
        }
        // B tile: 32 k x 64 n (2048 floats / 512 thr = 1 float4 each)
        {
            int kk = tid >> 4;               // 0..31
            int c4 = tid & 15;               // 0..15
            *(float4*)&Bs[kk][c4 * 4] = *(const float4*)&W[(k0 + kk) * NG + n0 + c4 * 4];
        }
        __syncthreads();

        #pragma unroll
        for (int k = 0; k < 32; k++) {
            float4 Af = *(const float4*)&As[k][tm * 4];
            float4 Bf = *(const float4*)&Bs[k][tn * 4];
            u64 a0 = pack2(Af.x, Af.y);
            u64 a1 = pack2(Af.z, Af.w);
            u64 b0 = dup2(Bf.x), b1 = dup2(Bf.y), b2 = dup2(Bf.z), b3 = dup2(Bf.w);
            ffma2(acc[0][0], a0, b0); ffma2(acc[0][1], a0, b1);
            ffma2(acc[0][2], a0, b2); ffma2(acc[0][3], a0, b3);
            ffma2(acc[1][0], a1, b0); ffma2(acc[1][1], a1, b1);
            ffma2(acc[1][2], a1, b2); ffma2(acc[1][3], a1, b3);
        }
        __syncthreads();
    }

    // fused LSTM epilogue: this thread owns 4 batch rows x unit u
    const float* __restrict__ bias = LAYER2 ? g_b2 : g_b1;
    float* __restrict__ cs   = LAYER2 ? g_c2 : g_c1;
    float* __restrict__ hout = LAYER2 ? g_h2[1 - p] : g_h1[1 - p];

    const int n = n0 + tn * 4;
    const int u = n >> 2;
    float4 bv = *(const float4*)&bias[n];

    #pragma unroll
    for (int r = 0; r < 4; r++) {
        int bb = m0 + tm * 4 + r;
        int rp = r >> 1;
        float pf = ((r & 1) ? hi32(acc[rp][0]) : lo32(acc[rp][0])) + bv.x;
        float pi = ((r & 1) ? hi32(acc[rp][1]) : lo32(acc[rp][1])) + bv.y;
        float pc = ((r & 1) ? hi32(acc[rp][2]) : lo32(acc[rp][2])) + bv.z;
        float po = ((r & 1) ? hi32(acc[rp][3]) : lo32(acc[rp][3])) + bv.w;
        if (!LAYER2) {
            int row = tokens[bb * TSTEPS + t];
            float4 x = *(const float4*)&g_embW[(size_t)row * NG + n];
            pf += x.x; pi += x.y; pc += x.z; po += x.w;
        }
        float gf = sigmoidf_(pf);
        float gi = sigmoidf_(pi);
        float ct = tanhf(pc);
        float go = sigmoidf_(po);
        float c  = cs[bb * UDIM + u];
        c = gf * c + gi * ct;
        cs[bb * UDIM + u] = c;
        hout[bb * UDIM + u] = go * tanhf(c);
    }
}

// ---------------- persistent all-timesteps kernel ----------------
__global__ __launch_bounds__(NTHR, 1) void lstm_persistent(
    const int* __restrict__ tokens,
    const float* __restrict__ w_out, const float* __restrict__ b_out,
    float* __restrict__ out)
{
    __shared__ __align__(16) float As[32][128];
    __shared__ __align__(16) float Bs[32][64];

    const int cta = blockIdx.x;
    const int n0  = (cta & 15) * 64;
    const int m0  = (cta >> 4) * 128;
    const int tm  = threadIdx.x >> 4;    // 0..31
    const int tn  = threadIdx.x & 15;    // 0..15

    for (int t = 0; t < TSTEPS; t++) {
        int p = t & 1;
        phase<false>(t, p, m0, n0, tm, tn, As, Bs, tokens);
        grid_barrier();
        phase<true >(t, p, m0, n0, tm, tn, As, Bs, tokens);
        grid_barrier();
    }

    // final dense + sigmoid: 8 batches per CTA (warps 0-7)
    int warp = threadIdx.x >> 5;
    int lane = threadIdx.x & 31;
    if (warp < 8) {
        int bb = cta * 8 + warp;
        const float* h = g_h2[0];        // t=79 (p=1) wrote buffer 0
        float s = 0.0f;
        #pragma unroll
        for (int i = 0; i < 8; i++)
            s += h[bb * UDIM + lane + i * 32] * w_out[lane + i * 32];
        #pragma unroll
        for (int o = 16; o; o >>= 1) s += __shfl_xor_sync(0xFFFFFFFFu, s, o);
        if (lane == 0) out[bb] = sigmoidf_(s + b_out[0]);
    }
}

// ---------------- launch ----------------
extern "C" void kernel_launch(void* const* d_in, const int* in_sizes, int n_in,
                              void* d_out, int out_size)
{
    const int*   tokens = (const int*)  d_in[0];
    const float* emb    = (const float*)d_in[1];
    const float* wf1 = (const float*)d_in[2];  const float* bf1 = (const float*)d_in[3];
    const float* wi1 = (const float*)d_in[4];  const float* bi1 = (const float*)d_in[5];
    const float* wc1 = (const float*)d_in[6];  const float* bc1 = (const float*)d_in[7];
    const float* wo1 = (const float*)d_in[8];  const float* bo1 = (const float*)d_in[9];
    const float* wf2 = (const float*)d_in[10]; const float* bf2 = (const float*)d_in[11];
    const float* wi2 = (const float*)d_in[12]; const float* bi2 = (const float*)d_in[13];
    const float* wc2 = (const float*)d_in[14]; const float* bc2 = (const float*)d_in[15];
    const float* wo2 = (const float*)d_in[16]; const float* bo2 = (const float*)d_in[17];
    const float* w_out = (const float*)d_in[18];
    const float* b_out = (const float*)d_in[19];
    float* out = (float*)d_out;

    const int TOT = (UDIM + EDIM + 2 * UDIM) * NG + 2 * NG;
    pack_kernel<<<(TOT + 255) / 256, 256>>>(wf1, bf1, wi1, bi1, wc1, bc1, wo1, bo1,
                                            wf2, bf2, wi2, bi2, wc2, bc2, wo2, bo2);
    zero_kernel<<<(BATCH * UDIM + 255) / 256, 256>>>();

    // embW = emb @ W1x  (V=10000 rows -> replaces the 81920-row xg GEMM)
    embw_kernel<<<dim3(NG / 64, (VOCAB + 63) / 64), 256>>>(emb);

    lstm_persistent<<<GRID_CTAS, NTHR>>>(tokens, w_out, b_out, out);
}